// round 8
// baseline (speedup 1.0000x reference)
#include <cuda_runtime.h>

// SpatialTransformer: vol [B=2,192,192,192,1] fp32, affine [B,3,4] fp32.
// Shared-memory tiled gather: each block stages the (near-identity-affine)
// input box for a 32x16x16 output tile into smem, then trilinear-samples
// from smem with conflict-free LDS. Global-gather fallback if the box
// exceeds capacity (correctness-safe for arbitrary affines).

#define DIM   192
#define SLAB  (DIM * DIM)      // 36864
#define BATCH 2

#define TW 32
#define TH 16
#define TD 16
#define GH (DIM / TH)          // 12 h-tiles
#define GW (DIM / TW)          // 6  w-tiles

#define BWP 48                 // padded box width (floats, mult of 4)
#define BHP 24                 // padded box height (rows)
#define PD  (BHP * BWP)        // 1152 floats per d-slab
#define NF4 (BWP / 4)          // 12 float4 per row
#define BD_CAP 22
#define SMEM_FLOATS (BD_CAP * PD)       // 25344
#define SMEM_BYTES  (SMEM_FLOATS * 4)   // 101376

__constant__ float c_aff[BATCH * 12];

__device__ __forceinline__ int iclamp(int v, int lo, int hi) {
    return min(max(v, lo), hi);
}

__global__ __launch_bounds__(512, 2) void st_tile(
    const float* __restrict__ vol,
    float* __restrict__ out)
{
    extern __shared__ float sbuf[];

    const int tx = threadIdx.x;                 // 0..31 : w (1 voxel/thread)
    const int ty = threadIdx.y;                 // 0..3  : h sub-row
    const int tz = threadIdx.z;                 // 0..3  : d sub-slab
    const int tid = tx + 32 * ty + 128 * tz;

    const int w0 = blockIdx.x * TW;
    const int hy = blockIdx.y;                  // h-tile + GH * d-tile
    const int h0 = (hy % GH) * TH;
    const int d0 = (hy / GH) * TD;
    const int b  = blockIdx.z;

    const float ctr  = (DIM - 1) * 0.5f;        // 95.5
    const float maxl = (float)(DIM - 1);        // 191

    const float* A = c_aff + b * 12;
    const float a00 = A[0], a01 = A[1],  a02 = A[2],  a03 = A[3];
    const float a10 = A[4], a11 = A[5],  a12 = A[6],  a13 = A[7];
    const float a20 = A[8], a21 = A[9],  a22 = A[10], a23 = A[11];

    // ---- input bounding box via separable corner extrema (uniform) ----
    const float cdl = (float)d0 - ctr,            cdh = (float)(d0 + TD - 1) - ctr;
    const float chl = (float)h0 - ctr,            chh = (float)(h0 + TH - 1) - ctr;
    const float cwl = (float)w0 - ctr,            cwh = (float)(w0 + TW - 1) - ctr;

    const float lo_d = a03 + ctr + fminf(a00 * cdl, a00 * cdh)
                               + fminf(a01 * chl, a01 * chh)
                               + fminf(a02 * cwl, a02 * cwh);
    const float hi_d = a03 + ctr + fmaxf(a00 * cdl, a00 * cdh)
                               + fmaxf(a01 * chl, a01 * chh)
                               + fmaxf(a02 * cwl, a02 * cwh);
    const float lo_h = a13 + ctr + fminf(a10 * cdl, a10 * cdh)
                               + fminf(a11 * chl, a11 * chh)
                               + fminf(a12 * cwl, a12 * cwh);
    const float hi_h = a13 + ctr + fmaxf(a10 * cdl, a10 * cdh)
                               + fmaxf(a11 * chl, a11 * chh)
                               + fmaxf(a12 * cwl, a12 * cwh);
    const float lo_w = a23 + ctr + fminf(a20 * cdl, a20 * cdh)
                               + fminf(a21 * chl, a21 * chh)
                               + fminf(a22 * cwl, a22 * cwh);
    const float hi_w = a23 + ctr + fmaxf(a20 * cdl, a20 * cdh)
                               + fmaxf(a21 * chl, a21 * chh)
                               + fmaxf(a22 * cwl, a22 * cwh);

    // ±1 guard margin covers fp discrepancy between corner extrema and the
    // per-voxel fma chains; +2 on the hi side covers the +1 ceil corner.
    const int bd0 = iclamp((int)floorf(lo_d) - 1, 0, DIM - 1);
    const int bd1 = iclamp((int)floorf(hi_d) + 2, 0, DIM - 1);
    const int bh0 = iclamp((int)floorf(lo_h) - 1, 0, DIM - 1);
    const int bh1 = iclamp((int)floorf(hi_h) + 2, 0, DIM - 1);
    int       bw0 = iclamp((int)floorf(lo_w) - 1, 0, DIM - 1);
    const int bw1 = iclamp((int)floorf(hi_w) + 2, 0, DIM - 1);
    bw0 &= ~3;                                   // float4 alignment

    const int BD = bd1 - bd0 + 1;
    const int BH = bh1 - bh0 + 1;
    const int BW = bw1 - bw0 + 1;
    const bool use_smem = (BD <= BD_CAP) && (BH <= BHP) && (BW <= BWP);

    const float* vb = vol + (size_t)b * (DIM * SLAB);

    // ---- stage box into smem (coalesced float4, padded const strides) ----
    if (use_smem) {
        const int F = BD * (BHP * NF4);          // float4 chunks
        const float4* __restrict__ v4 = (const float4*)vb;
        float4* s4 = (float4*)sbuf;
        for (int t = tid; t < F; t += 512) {
            const int row = t / NF4;             // dd*BHP + hh   (const div)
            const int f   = t - row * NF4;
            const int dd  = row / BHP;           // const div
            const int hh  = row - dd * BHP;
            // clamp padded lanes into the volume (values unused by sampling)
            const int gd_ = min(bd0 + dd, DIM - 1);
            const int gh_ = min(bh0 + hh, DIM - 1);
            const int gw_ = min(bw0 + 4 * f, DIM - 4);
            s4[t] = v4[(gd_ * SLAB + gh_ * DIM + gw_) >> 2];
        }
        __syncthreads();
    }

    // ---- per-thread sample setup ----
    const float cd = (float)(d0 + tz) - ctr;
    const float ch = (float)(h0 + ty) - ctr;
    const float cw = (float)(w0 + tx) - ctr;

    const float ldB = fmaf(a00, cd, fmaf(a01, ch, fmaf(a02, cw, a03))) + ctr;
    const float lhB = fmaf(a10, cd, fmaf(a11, ch, fmaf(a12, cw, a13))) + ctr;
    const float lwB = fmaf(a20, cd, fmaf(a21, ch, fmaf(a22, cw, a23))) + ctr;

    const float a00_4 = 4.f * a00, a01_4 = 4.f * a01;
    const float a10_4 = 4.f * a10, a11_4 = 4.f * a11;
    const float a20_4 = 4.f * a20, a21_4 = 4.f * a21;

    const size_t obase = (((size_t)(b * DIM + d0 + tz)) * DIM + (h0 + ty)) * DIM
                         + (w0 + tx);

    if (use_smem) {
#pragma unroll
        for (int jd = 0; jd < 4; jd++) {
            const float jdF = (float)jd;
            const float ld_d = fmaf(a00_4, jdF, ldB);
            const float lh_d = fmaf(a10_4, jdF, lhB);
            const float lw_d = fmaf(a20_4, jdF, lwB);
#pragma unroll
            for (int jh = 0; jh < 4; jh++) {
                const float jhF = (float)jh;
                const float ldv = fmaf(a01_4, jhF, ld_d);
                const float lhv = fmaf(a11_4, jhF, lh_d);
                const float lwv = fmaf(a21_4, jhF, lw_d);

                const float sd = fminf(fmaxf(ldv, 0.f), maxl);
                const int   id = (int)sd;
                const float td = sd - (float)id;
                const int   od = (id < bd1) ? PD : 0;

                const float sh = fminf(fmaxf(lhv, 0.f), maxl);
                const int   ih = (int)sh;
                const float th = sh - (float)ih;
                const int   oh = (ih < bh1) ? BWP : 0;

                const float sw = fminf(fmaxf(lwv, 0.f), maxl);
                const int   iw = (int)sw;
                const float tw = sw - (float)iw;
                const int   ow = (iw < bw1) ? 1 : 0;

                const float* p = sbuf + ((id - bd0) * PD + (ih - bh0) * BWP
                                         + (iw - bw0));
                const float v000 = p[0];
                const float v001 = p[ow];
                const float v010 = p[oh];
                const float v011 = p[oh + ow];
                const float* q = p + od;
                const float v100 = q[0];
                const float v101 = q[ow];
                const float v110 = q[oh];
                const float v111 = q[oh + ow];

                const float p00 = fmaf(tw, v001 - v000, v000);
                const float p01 = fmaf(tw, v011 - v010, v010);
                const float p10 = fmaf(tw, v101 - v100, v100);
                const float p11 = fmaf(tw, v111 - v110, v110);
                const float q0  = fmaf(th, p01 - p00, p00);
                const float q1  = fmaf(th, p11 - p10, p10);
                const float res = fmaf(td, q1 - q0, q0);

                out[obase + (size_t)(jd * 4 * SLAB + jh * 4 * DIM)] = res;
            }
        }
    } else {
        // fallback: direct global gather (identical semantics)
#pragma unroll
        for (int jd = 0; jd < 4; jd++) {
            const float jdF = (float)jd;
            const float ld_d = fmaf(a00_4, jdF, ldB);
            const float lh_d = fmaf(a10_4, jdF, lhB);
            const float lw_d = fmaf(a20_4, jdF, lwB);
#pragma unroll
            for (int jh = 0; jh < 4; jh++) {
                const float jhF = (float)jh;
                const float ldv = fmaf(a01_4, jhF, ld_d);
                const float lhv = fmaf(a11_4, jhF, lh_d);
                const float lwv = fmaf(a21_4, jhF, lw_d);

                const float sd = fminf(fmaxf(ldv, 0.f), maxl);
                const int   id = (int)sd;
                const float td = sd - (float)id;
                const int   od = (id < DIM - 1) ? SLAB : 0;

                const float sh = fminf(fmaxf(lhv, 0.f), maxl);
                const int   ih = (int)sh;
                const float th = sh - (float)ih;
                const int   oh = (ih < DIM - 1) ? DIM : 0;

                const float sw = fminf(fmaxf(lwv, 0.f), maxl);
                const int   iw = (int)sw;
                const float tw = sw - (float)iw;
                const int   ow = (iw < DIM - 1) ? 1 : 0;

                const float* p = vb + (id * SLAB + ih * DIM + iw);
                const float v000 = __ldg(p);
                const float v001 = __ldg(p + ow);
                const float v010 = __ldg(p + oh);
                const float v011 = __ldg(p + oh + ow);
                const float* q = p + od;
                const float v100 = __ldg(q);
                const float v101 = __ldg(q + ow);
                const float v110 = __ldg(q + oh);
                const float v111 = __ldg(q + oh + ow);

                const float p00 = fmaf(tw, v001 - v000, v000);
                const float p01 = fmaf(tw, v011 - v010, v010);
                const float p10 = fmaf(tw, v101 - v100, v100);
                const float p11 = fmaf(tw, v111 - v110, v110);
                const float q0  = fmaf(th, p01 - p00, p00);
                const float q1  = fmaf(th, p11 - p10, p10);
                const float res = fmaf(td, q1 - q0, q0);

                out[obase + (size_t)(jd * 4 * SLAB + jh * 4 * DIM)] = res;
            }
        }
    }
}

extern "C" void kernel_launch(void* const* d_in, const int* in_sizes, int n_in,
                              void* d_out, int out_size)
{
    const float* vol = (const float*)d_in[0];
    const float* aff = (const float*)d_in[1];
    float* out = (float*)d_out;

    cudaFuncSetAttribute(st_tile, cudaFuncAttributeMaxDynamicSharedMemorySize,
                         SMEM_BYTES);
    cudaMemcpyToSymbolAsync(c_aff, aff, BATCH * 12 * sizeof(float), 0,
                            cudaMemcpyDeviceToDevice, 0);

    dim3 grid(GW, GH * (DIM / TD), BATCH);   // (6, 144, 2)
    dim3 block(32, 4, 4);                    // 512 threads
    st_tile<<<grid, block, SMEM_BYTES>>>(vol, out);
}

// round 9
// speedup vs baseline: 1.4117x; 1.4117x over previous
#include <cuda_runtime.h>

// SpatialTransformer: vol [B=2,192,192,192,1] fp32, affine [B,3,4] fp32.
// Direct-gather lerp kernel (R2 dataflow) with warp->w remapping:
// a warp's 32 lanes cover 32 consecutive w (4B stride), so each gather
// LDG.32 touches ~2 cache lines (2 L1 wavefronts) instead of 4.
// Per-thread x4 unroll runs along h instead of w.

#define DIM 192
#define SLAB (DIM * DIM)
#define BATCH 2
#define UH 4                    // voxels per thread along h

__constant__ float c_aff[BATCH * 12];

__global__ __launch_bounds__(DIM) void st_warp_h4(
    const float* __restrict__ vol,
    float* __restrict__ out)
{
    const int w  = threadIdx.x;             // 0..191, warp = 32 consecutive w
    const int h0 = blockIdx.x * UH;
    const int d  = blockIdx.y;
    const int b  = blockIdx.z;

    const float ctr  = (DIM - 1) * 0.5f;    // 95.5
    const float maxl = (float)(DIM - 1);    // 191

    const float* A = c_aff + b * 12;
    const float a00 = A[0], a01 = A[1],  a02 = A[2],  a03 = A[3];
    const float a10 = A[4], a11 = A[5],  a12 = A[6],  a13 = A[7];
    const float a20 = A[8], a21 = A[9],  a22 = A[10], a23 = A[11];

    const float cd = (float)d  - ctr;
    const float ch = (float)h0 - ctr;
    const float cw = (float)w  - ctr;

    // Sample location at j=0; along h it advances by (a01, a11, a21)/voxel.
    const float ld0 = fmaf(a00, cd, fmaf(a01, ch, fmaf(a02, cw, a03))) + ctr;
    const float lh0 = fmaf(a10, cd, fmaf(a11, ch, fmaf(a12, cw, a13))) + ctr;
    const float lw0 = fmaf(a20, cd, fmaf(a21, ch, fmaf(a22, cw, a23))) + ctr;

    const float* vb = vol + (size_t)b * (DIM * SLAB);
    float* ob = out + ((size_t)(b * DIM + d) * DIM + h0) * DIM + w;

#pragma unroll
    for (int j = 0; j < UH; j++) {
        const float fj = (float)j;
        const float ldv = fmaf(a01, fj, ld0);
        const float lhv = fmaf(a11, fj, lh0);
        const float lwv = fmaf(a21, fj, lw0);

        // clamp / floor-as-trunc / frac / edge step-select; matches the
        // reference clip(floor), clip(l0+1) semantics exactly (at the upper
        // edge v1==v0 so t is irrelevant; at the lower edge t=0 picks v0).
        const float sd = fminf(fmaxf(ldv, 0.f), maxl);
        const int   id = (int)sd;
        const float td = sd - (float)id;
        const int   od = (id < DIM - 1) ? SLAB : 0;

        const float sh = fminf(fmaxf(lhv, 0.f), maxl);
        const int   ih = (int)sh;
        const float th = sh - (float)ih;
        const int   oh = (ih < DIM - 1) ? DIM : 0;

        const float sw = fminf(fmaxf(lwv, 0.f), maxl);
        const int   iw = (int)sw;
        const float tw = sw - (float)iw;
        const int   ow = (iw < DIM - 1) ? 1 : 0;

        const float* p = vb + (id * SLAB + ih * DIM + iw);

        const float v000 = __ldg(p);
        const float v001 = __ldg(p + ow);
        const float v010 = __ldg(p + oh);
        const float v011 = __ldg(p + oh + ow);
        const float* q = p + od;
        const float v100 = __ldg(q);
        const float v101 = __ldg(q + ow);
        const float v110 = __ldg(q + oh);
        const float v111 = __ldg(q + oh + ow);

        const float p00 = fmaf(tw, v001 - v000, v000);
        const float p01 = fmaf(tw, v011 - v010, v010);
        const float p10 = fmaf(tw, v101 - v100, v100);
        const float p11 = fmaf(tw, v111 - v110, v110);

        const float q0 = fmaf(th, p01 - p00, p00);
        const float q1 = fmaf(th, p11 - p10, p10);

        ob[(size_t)j * DIM] = fmaf(td, q1 - q0, q0);
    }
}

extern "C" void kernel_launch(void* const* d_in, const int* in_sizes, int n_in,
                              void* d_out, int out_size)
{
    const float* vol = (const float*)d_in[0];
    const float* aff = (const float*)d_in[1];
    float* out = (float*)d_out;

    cudaMemcpyToSymbolAsync(c_aff, aff, BATCH * 12 * sizeof(float), 0,
                            cudaMemcpyDeviceToDevice, 0);

    dim3 grid(DIM / UH, DIM, BATCH);   // (48, 192, 2)
    dim3 block(DIM);                   // 192 threads, warp = 32 consecutive w
    st_warp_h4<<<grid, block>>>(vol, out);
}

// round 10
// speedup vs baseline: 1.6028x; 1.1353x over previous
#include <cuda_runtime.h>

// SpatialTransformer: vol [B=2,192,192,192,1] fp32, affine [B,3,4] fp32.
// Warp = 32 consecutive w; 4 voxels/thread along h. Warp-uniform interior
// fast path (d,h strictly inside): no clamp/select for d,h and all 8 gathers
// use compile-time immediate offsets off two base pointers. w stays fully
// general so w-edge warps still take the fast path. Slow path = exact
// general clamp logic (reference semantics) for d/h-edge warps.

#define DIM 192
#define SLAB (DIM * DIM)
#define BATCH 2
#define UH 4

__constant__ float c_aff[BATCH * 12];

__global__ __launch_bounds__(DIM) void st_warp_fast(
    const float* __restrict__ vol,
    float* __restrict__ out)
{
    const int w  = threadIdx.x;             // warp = 32 consecutive w
    const int h0 = blockIdx.x * UH;
    const int d  = blockIdx.y;
    const int b  = blockIdx.z;

    const float ctr  = (DIM - 1) * 0.5f;    // 95.5
    const float maxl = (float)(DIM - 1);    // 191

    const float* A = c_aff + b * 12;
    const float a00 = A[0], a01 = A[1],  a02 = A[2],  a03 = A[3];
    const float a10 = A[4], a11 = A[5],  a12 = A[6],  a13 = A[7];
    const float a20 = A[8], a21 = A[9],  a22 = A[10], a23 = A[11];

    const float cd = (float)d  - ctr;
    const float ch = (float)h0 - ctr;
    const float cw = (float)w  - ctr;

    // Sample location at j=0; along h it advances by (a01, a11, a21)/voxel.
    const float ld0 = fmaf(a00, cd, fmaf(a01, ch, fmaf(a02, cw, a03))) + ctr;
    const float lh0 = fmaf(a10, cd, fmaf(a11, ch, fmaf(a12, cw, a13))) + ctr;
    const float lw0 = fmaf(a20, cd, fmaf(a21, ch, fmaf(a22, cw, a23))) + ctr;

    const float* vb = vol + (size_t)b * (DIM * SLAB);
    float* ob = out + ((size_t)(b * DIM + d) * DIM + h0) * DIM + w;

    // ---- warp-uniform interior test for d,h dims (separable extrema) ----
    const int   wlo = w & ~31;
    const float chl = (float)h0 - ctr,            chh = (float)(h0 + UH - 1) - ctr;
    const float cwl = (float)wlo - ctr,           cwh = (float)(wlo + 31) - ctr;

    const float bas_d = a00 * cd + a03 + ctr;
    const float lo_d  = bas_d + fminf(a01 * chl, a01 * chh) + fminf(a02 * cwl, a02 * cwh);
    const float hi_d  = bas_d + fmaxf(a01 * chl, a01 * chh) + fmaxf(a02 * cwl, a02 * cwh);
    const float bas_h = a10 * cd + a13 + ctr;
    const float lo_h  = bas_h + fminf(a11 * chl, a11 * chh) + fminf(a12 * cwl, a12 * cwh);
    const float hi_h  = bas_h + fmaxf(a11 * chl, a11 * chh) + fmaxf(a12 * cwl, a12 * cwh);

    // 0.5 guard >> fp discrepancy (~1e-4) between extrema and fma chains.
    const bool fast = (lo_d > 0.5f) & (hi_d < 190.5f) &
                      (lo_h > 0.5f) & (hi_h < 190.5f);

    if (fast) {
#pragma unroll
        for (int j = 0; j < UH; j++) {
            const float fj = (float)j;
            const float ldv = fmaf(a01, fj, ld0);
            const float lhv = fmaf(a11, fj, lh0);
            const float lwv = fmaf(a21, fj, lw0);

            // interior d,h: trunc==floor, no clamp, id+1/ih+1 in range
            const int   id = (int)ldv;
            const float td = ldv - (float)id;
            const int   ih = (int)lhv;
            const float th = lhv - (float)ih;

            // w fully general (handles w edges inside fast warps)
            const float sw = fminf(fmaxf(lwv, 0.f), maxl);
            const int   iw = (int)sw;
            const float tw = sw - (float)iw;
            const int   ow = (iw < DIM - 1) ? 1 : 0;

            const float* p  = vb + (id * SLAB + ih * DIM + iw);
            const float* p2 = p + ow;

            const float v000 = __ldg(p);
            const float v001 = __ldg(p2);
            const float v010 = __ldg(p  + DIM);
            const float v011 = __ldg(p2 + DIM);
            const float v100 = __ldg(p  + SLAB);
            const float v101 = __ldg(p2 + SLAB);
            const float v110 = __ldg(p  + SLAB + DIM);
            const float v111 = __ldg(p2 + SLAB + DIM);

            const float p00 = fmaf(tw, v001 - v000, v000);
            const float p01 = fmaf(tw, v011 - v010, v010);
            const float p10 = fmaf(tw, v101 - v100, v100);
            const float p11 = fmaf(tw, v111 - v110, v110);
            const float q0  = fmaf(th, p01 - p00, p00);
            const float q1  = fmaf(th, p11 - p10, p10);

            ob[(size_t)j * DIM] = fmaf(td, q1 - q0, q0);
        }
    } else {
        // general path: exact reference clamp semantics in every dim
#pragma unroll
        for (int j = 0; j < UH; j++) {
            const float fj = (float)j;
            const float ldv = fmaf(a01, fj, ld0);
            const float lhv = fmaf(a11, fj, lh0);
            const float lwv = fmaf(a21, fj, lw0);

            const float sd = fminf(fmaxf(ldv, 0.f), maxl);
            const int   id = (int)sd;
            const float td = sd - (float)id;
            const int   od = (id < DIM - 1) ? SLAB : 0;

            const float sh = fminf(fmaxf(lhv, 0.f), maxl);
            const int   ih = (int)sh;
            const float th = sh - (float)ih;
            const int   oh = (ih < DIM - 1) ? DIM : 0;

            const float sw = fminf(fmaxf(lwv, 0.f), maxl);
            const int   iw = (int)sw;
            const float tw = sw - (float)iw;
            const int   ow = (iw < DIM - 1) ? 1 : 0;

            const float* p = vb + (id * SLAB + ih * DIM + iw);

            const float v000 = __ldg(p);
            const float v001 = __ldg(p + ow);
            const float v010 = __ldg(p + oh);
            const float v011 = __ldg(p + oh + ow);
            const float* q = p + od;
            const float v100 = __ldg(q);
            const float v101 = __ldg(q + ow);
            const float v110 = __ldg(q + oh);
            const float v111 = __ldg(q + oh + ow);

            const float p00 = fmaf(tw, v001 - v000, v000);
            const float p01 = fmaf(tw, v011 - v010, v010);
            const float p10 = fmaf(tw, v101 - v100, v100);
            const float p11 = fmaf(tw, v111 - v110, v110);
            const float q0  = fmaf(th, p01 - p00, p00);
            const float q1  = fmaf(th, p11 - p10, p10);

            ob[(size_t)j * DIM] = fmaf(td, q1 - q0, q0);
        }
    }
}

extern "C" void kernel_launch(void* const* d_in, const int* in_sizes, int n_in,
                              void* d_out, int out_size)
{
    const float* vol = (const float*)d_in[0];
    const float* aff = (const float*)d_in[1];
    float* out = (float*)d_out;

    cudaMemcpyToSymbolAsync(c_aff, aff, BATCH * 12 * sizeof(float), 0,
                            cudaMemcpyDeviceToDevice, 0);

    dim3 grid(DIM / UH, DIM, BATCH);   // (48, 192, 2)
    dim3 block(DIM);                   // 192 threads, warp = 32 consecutive w
    st_warp_fast<<<grid, block>>>(vol, out);
}

// round 11
// speedup vs baseline: 1.7799x; 1.1105x over previous
#include <cuda_runtime.h>

// SpatialTransformer: vol [B=2,192,192,192,1] fp32, affine [B,3,4] fp32.
// Warp = 32 consecutive w; 8 voxels/thread along h. Three warp-uniform paths:
//   A: d,h,w all strictly interior -> no clamps/selects, 8 gathers at
//      compile-time immediate offsets off ONE base pointer.
//   B: d,h interior, w general     -> R5 fast path.
//   C: fully general               -> exact reference clamp semantics.
// Affine read directly from gmem (no memcpy graph node).

#define DIM 192
#define SLAB (DIM * DIM)
#define BATCH 2
#define UH 8

__global__ __launch_bounds__(DIM, 8) void st_warp3(
    const float* __restrict__ vol,
    const float* __restrict__ aff,
    float* __restrict__ out)
{
    const int w  = threadIdx.x;             // warp = 32 consecutive w
    const int h0 = blockIdx.x * UH;
    const int d  = blockIdx.y;
    const int b  = blockIdx.z;

    const float ctr  = (DIM - 1) * 0.5f;    // 95.5
    const float maxl = (float)(DIM - 1);    // 191

    const float* A = aff + b * 12;          // warp-uniform, L1-hit
    const float a00 = __ldg(A + 0), a01 = __ldg(A + 1),  a02 = __ldg(A + 2),  a03 = __ldg(A + 3);
    const float a10 = __ldg(A + 4), a11 = __ldg(A + 5),  a12 = __ldg(A + 6),  a13 = __ldg(A + 7);
    const float a20 = __ldg(A + 8), a21 = __ldg(A + 9),  a22 = __ldg(A + 10), a23 = __ldg(A + 11);

    const float cd = (float)d  - ctr;
    const float ch = (float)h0 - ctr;
    const float cw = (float)w  - ctr;

    // Sample location at j=0; along h it advances by (a01, a11, a21)/voxel.
    const float ld0 = fmaf(a00, cd, fmaf(a01, ch, fmaf(a02, cw, a03))) + ctr;
    const float lh0 = fmaf(a10, cd, fmaf(a11, ch, fmaf(a12, cw, a13))) + ctr;
    const float lw0 = fmaf(a20, cd, fmaf(a21, ch, fmaf(a22, cw, a23))) + ctr;

    const float* vb = vol + (size_t)b * (DIM * SLAB);
    float* ob = out + ((size_t)(b * DIM + d) * DIM + h0) * DIM + w;

    // ---- warp-uniform interior tests (separable corner extrema) ----
    const int   wlo = w & ~31;
    const float chl = (float)h0 - ctr,  chh = (float)(h0 + UH - 1) - ctr;
    const float cwl = (float)wlo - ctr, cwh = (float)(wlo + 31) - ctr;

    const float bas_d = a00 * cd + a03 + ctr;
    const float lo_d  = bas_d + fminf(a01 * chl, a01 * chh) + fminf(a02 * cwl, a02 * cwh);
    const float hi_d  = bas_d + fmaxf(a01 * chl, a01 * chh) + fmaxf(a02 * cwl, a02 * cwh);
    const float bas_h = a10 * cd + a13 + ctr;
    const float lo_h  = bas_h + fminf(a11 * chl, a11 * chh) + fminf(a12 * cwl, a12 * cwh);
    const float hi_h  = bas_h + fmaxf(a11 * chl, a11 * chh) + fmaxf(a12 * cwl, a12 * cwh);
    const float bas_w = a20 * cd + a23 + ctr;
    const float lo_w  = bas_w + fminf(a21 * chl, a21 * chh) + fminf(a22 * cwl, a22 * cwh);
    const float hi_w  = bas_w + fmaxf(a21 * chl, a21 * chh) + fmaxf(a22 * cwl, a22 * cwh);

    // 0.5 guard >> fp discrepancy (~1e-4) between extrema and fma chains.
    const bool dh_int = (lo_d > 0.5f) & (hi_d < 190.5f) &
                        (lo_h > 0.5f) & (hi_h < 190.5f);
    const bool w_int  = (lo_w > 0.5f) & (hi_w < 190.5f);

    if (dh_int & w_int) {
        // ---- path A: fully interior, single base, immediate offsets ----
#pragma unroll
        for (int j = 0; j < UH; j++) {
            const float fj = (float)j;
            const float ldv = fmaf(a01, fj, ld0);
            const float lhv = fmaf(a11, fj, lh0);
            const float lwv = fmaf(a21, fj, lw0);

            const int   id = (int)ldv;  const float td = ldv - (float)id;
            const int   ih = (int)lhv;  const float th = lhv - (float)ih;
            const int   iw = (int)lwv;  const float tw = lwv - (float)iw;

            const float* p = vb + (id * SLAB + ih * DIM + iw);

            const float v000 = __ldg(p);
            const float v001 = __ldg(p + 1);
            const float v010 = __ldg(p + DIM);
            const float v011 = __ldg(p + DIM + 1);
            const float v100 = __ldg(p + SLAB);
            const float v101 = __ldg(p + SLAB + 1);
            const float v110 = __ldg(p + SLAB + DIM);
            const float v111 = __ldg(p + SLAB + DIM + 1);

            const float p00 = fmaf(tw, v001 - v000, v000);
            const float p01 = fmaf(tw, v011 - v010, v010);
            const float p10 = fmaf(tw, v101 - v100, v100);
            const float p11 = fmaf(tw, v111 - v110, v110);
            const float q0  = fmaf(th, p01 - p00, p00);
            const float q1  = fmaf(th, p11 - p10, p10);

            ob[(size_t)j * DIM] = fmaf(td, q1 - q0, q0);
        }
    } else if (dh_int) {
        // ---- path B: d,h interior; w general (handles w edges) ----
#pragma unroll
        for (int j = 0; j < UH; j++) {
            const float fj = (float)j;
            const float ldv = fmaf(a01, fj, ld0);
            const float lhv = fmaf(a11, fj, lh0);
            const float lwv = fmaf(a21, fj, lw0);

            const int   id = (int)ldv;  const float td = ldv - (float)id;
            const int   ih = (int)lhv;  const float th = lhv - (float)ih;

            const float sw = fminf(fmaxf(lwv, 0.f), maxl);
            const int   iw = (int)sw;
            const float tw = sw - (float)iw;
            const int   ow = (iw < DIM - 1) ? 1 : 0;

            const float* p  = vb + (id * SLAB + ih * DIM + iw);
            const float* p2 = p + ow;

            const float v000 = __ldg(p);
            const float v001 = __ldg(p2);
            const float v010 = __ldg(p  + DIM);
            const float v011 = __ldg(p2 + DIM);
            const float v100 = __ldg(p  + SLAB);
            const float v101 = __ldg(p2 + SLAB);
            const float v110 = __ldg(p  + SLAB + DIM);
            const float v111 = __ldg(p2 + SLAB + DIM);

            const float p00 = fmaf(tw, v001 - v000, v000);
            const float p01 = fmaf(tw, v011 - v010, v010);
            const float p10 = fmaf(tw, v101 - v100, v100);
            const float p11 = fmaf(tw, v111 - v110, v110);
            const float q0  = fmaf(th, p01 - p00, p00);
            const float q1  = fmaf(th, p11 - p10, p10);

            ob[(size_t)j * DIM] = fmaf(td, q1 - q0, q0);
        }
    } else {
        // ---- path C: fully general (exact reference clamp semantics) ----
#pragma unroll
        for (int j = 0; j < UH; j++) {
            const float fj = (float)j;
            const float ldv = fmaf(a01, fj, ld0);
            const float lhv = fmaf(a11, fj, lh0);
            const float lwv = fmaf(a21, fj, lw0);

            const float sd = fminf(fmaxf(ldv, 0.f), maxl);
            const int   id = (int)sd;
            const float td = sd - (float)id;
            const int   od = (id < DIM - 1) ? SLAB : 0;

            const float sh = fminf(fmaxf(lhv, 0.f), maxl);
            const int   ih = (int)sh;
            const float th = sh - (float)ih;
            const int   oh = (ih < DIM - 1) ? DIM : 0;

            const float sw = fminf(fmaxf(lwv, 0.f), maxl);
            const int   iw = (int)sw;
            const float tw = sw - (float)iw;
            const int   ow = (iw < DIM - 1) ? 1 : 0;

            const float* p = vb + (id * SLAB + ih * DIM + iw);

            const float v000 = __ldg(p);
            const float v001 = __ldg(p + ow);
            const float v010 = __ldg(p + oh);
            const float v011 = __ldg(p + oh + ow);
            const float* q = p + od;
            const float v100 = __ldg(q);
            const float v101 = __ldg(q + ow);
            const float v110 = __ldg(q + oh);
            const float v111 = __ldg(q + oh + ow);

            const float p00 = fmaf(tw, v001 - v000, v000);
            const float p01 = fmaf(tw, v011 - v010, v010);
            const float p10 = fmaf(tw, v101 - v100, v100);
            const float p11 = fmaf(tw, v111 - v110, v110);
            const float q0  = fmaf(th, p01 - p00, p00);
            const float q1  = fmaf(th, p11 - p10, p10);

            ob[(size_t)j * DIM] = fmaf(td, q1 - q0, q0);
        }
    }
}

extern "C" void kernel_launch(void* const* d_in, const int* in_sizes, int n_in,
                              void* d_out, int out_size)
{
    const float* vol = (const float*)d_in[0];
    const float* aff = (const float*)d_in[1];
    float* out = (float*)d_out;

    dim3 grid(DIM / UH, DIM, BATCH);   // (24, 192, 2)
    dim3 block(DIM);                   // 192 threads, warp = 32 consecutive w
    st_warp3<<<grid, block>>>(vol, aff, out);
}